// round 4
// baseline (speedup 1.0000x reference)
#include <cuda_runtime.h>
#include <math.h>

#define KC 16
#define DD 64
#define NMAX 204800

// Precomputed per-component data: W = L^{-1} (lower-tri), t = W*mu,
// c = log(pi) - 0.5*D*log(2pi) - sum(log(diag(L)))
__device__ float g_W[KC][DD][DD];
__device__ float g_t[KC][DD];
__device__ float g_c[KC];
__device__ float g_logits[KC][NMAX];   // [K][N] scratch, coalesced writes

// ---------------- packed f32x2 helpers ----------------
__device__ __forceinline__ unsigned long long fma2(unsigned long long a,
                                                   unsigned long long b,
                                                   unsigned long long c) {
    unsigned long long d;
    asm("fma.rn.f32x2 %0, %1, %2, %3;" : "=l"(d) : "l"(a), "l"(b), "l"(c));
    return d;
}
__device__ __forceinline__ unsigned long long add2(unsigned long long a,
                                                   unsigned long long b) {
    unsigned long long d;
    asm("add.rn.f32x2 %0, %1, %2;" : "=l"(d) : "l"(a), "l"(b));
    return d;
}
__device__ __forceinline__ unsigned long long pk2(float lo, float hi) {
    unsigned long long r;
    asm("mov.b64 %0, {%1, %2};" : "=l"(r) : "f"(lo), "f"(hi));
    return r;
}
__device__ __forceinline__ float2 unpk2(unsigned long long v) {
    unsigned int lo, hi;
    asm("mov.b64 {%0, %1}, %2;" : "=r"(lo), "=r"(hi) : "l"(v));
    float2 f;
    f.x = __uint_as_float(lo);
    f.y = __uint_as_float(hi);
    return f;
}

// ---------------- cp.async helpers ----------------
__device__ __forceinline__ unsigned smem_u32(const void* p) {
    return (unsigned)__cvta_generic_to_shared(p);
}
__device__ __forceinline__ void cp16(unsigned dst, const void* src) {
    asm volatile("cp.async.cg.shared.global [%0], [%1], 16;\n"
                 :: "r"(dst), "l"(src));
}
__device__ __forceinline__ void cp_commit() {
    asm volatile("cp.async.commit_group;\n");
}
template <int N> __device__ __forceinline__ void cp_wait() {
    asm volatile("cp.async.wait_group %0;\n" :: "n"(N));
}

// ---------------- precompute v2: register-resident, fully unrolled --------
// 16 blocks (one per component) x 64 threads; thread c owns COLUMN c.
__global__ void __launch_bounds__(64)
gmm_precompute_kernel(const float* __restrict__ pi,
                      const float* __restrict__ mus,
                      const float* __restrict__ covs) {
    __shared__ float colbuf[2][DD];   // broadcast column (double-buffered)
    __shared__ float diag[DD];        // L diagonal
    __shared__ float sinv[DD];        // 1 / L diagonal
    __shared__ float mu_s[DD];
    __shared__ float ts[DD];
    __shared__ float Ms[DD][DD + 1];  // L, then W

    const int k = blockIdx.x;
    const int c = threadIdx.x;  // 0..63, owns column c

    // load column c of cov (coalesced across threads per row i)
    float a[DD];
#pragma unroll
    for (int i = 0; i < DD; i++)
        a[i] = covs[((size_t)k * DD + i) * DD + c];
    mu_s[c] = mus[k * DD + c];

    // ---- right-looking Cholesky: after loop, a[i] (i>=c) = L[i][c] ----
#pragma unroll
    for (int j = 0; j < DD; j++) {
        float* col = colbuf[j & 1];
        if (c == j) {
#pragma unroll
            for (int i = j; i < DD; i++) col[i] = a[i];  // raw Schur column
        }
        __syncthreads();
        const float dj = col[j];
        if (c == j) {
            const float ljj = sqrtf(dj);
            const float inv = 1.0f / ljj;
            diag[j] = ljj;
            sinv[j] = inv;
            a[j] = ljj;
#pragma unroll
            for (int i = j + 1; i < DD; i++) a[i] *= inv;
        } else if (c > j) {
            const float s = col[c] / dj;
#pragma unroll
            for (int i = 0; i < DD; i++)
                if (i >= c) a[i] -= col[i] * s;  // predicated, regs static
        }
    }

    // store L (column c) into Ms, zero upper triangle
#pragma unroll
    for (int i = 0; i < DD; i++) Ms[i][c] = (i >= c) ? a[i] : 0.0f;
    __syncthreads();

    // ---- triangular inverse: w[] = column c of W = L^{-1} ----
    float w[DD];
#pragma unroll
    for (int i = 0; i < DD; i++) w[i] = (i == c) ? 1.0f : 0.0f;
#pragma unroll
    for (int j = 0; j < DD; j++) {
        const float wj = w[j] * sinv[j];   // 0 for j < c (w[j]==0)
        w[j] = wj;
#pragma unroll
        for (int i = j + 1; i < DD; i++)
            w[i] -= Ms[i][j] * wj;         // broadcast LDS, indep over i
    }

    // write W rows to gmem (coalesced across c per row i)
#pragma unroll
    for (int i = 0; i < DD; i++) g_W[k][i][c] = w[i];

    // store W into Ms (overwrite L; fully consumed above)
    __syncthreads();
#pragma unroll
    for (int i = 0; i < DD; i++) Ms[i][c] = w[i];
    __syncthreads();

    // t[c] = row c of W dot mu
    {
        float s = 0.0f;
#pragma unroll
        for (int j = 0; j < DD; j++)
            s = fmaf(Ms[c][j], mu_s[j], s);
        g_t[k][c] = s;
        ts[c] = s;
    }
    __syncthreads();
    if (c == 0) {
        float hld = 0.0f;
        for (int i = 0; i < DD; i++) hld += logf(diag[i]);
        g_c[k] = logf(pi[k]) - 32.0f * 1.8378770664093453f - hld;
    }
}

// ---------------- main kernel ----------------
// 128 threads/block, TWO points per thread, triangular matvec, 4 CTAs/SM.
__global__ __launch_bounds__(128, 4)
void gmm_main_kernel(const float* __restrict__ X, int n) {
    __shared__ __align__(16) float Ws[2][DD * DD];  // 2 x 16 KB
    __shared__ __align__(16) float ts[2][DD];
    __shared__ float cs[KC];

    const int tid = threadIdx.x;
    const int p0 = (blockIdx.x * 128 + tid) * 2;
    const int ld0 = (p0 < n) ? p0 : (n - 1);
    const int ld1 = (p0 + 1 < n) ? (p0 + 1) : (n - 1);

    if (tid < KC) cs[tid] = g_c[tid];

    // Load both points into packed f32x2 registers (j-packing)
    unsigned long long pxA[DD / 2], pxB[DD / 2];
    {
        const float4* xr0 = (const float4*)(X + (size_t)ld0 * DD);
        const float4* xr1 = (const float4*)(X + (size_t)ld1 * DD);
#pragma unroll
        for (int i = 0; i < DD / 4; i++) {
            float4 v = xr0[i];
            pxA[2 * i]     = pk2(v.x, v.y);
            pxA[2 * i + 1] = pk2(v.z, v.w);
            float4 u = xr1[i];
            pxB[2 * i]     = pk2(u.x, u.y);
            pxB[2 * i + 1] = pk2(u.z, u.w);
        }
    }

    // prefetch component 0 into buffer 0
    {
        const float4* src = (const float4*)&g_W[0][0][0];
        unsigned dst = smem_u32(&Ws[0][0]);
#pragma unroll
        for (int i = 0; i < 8; i++)
            cp16(dst + (unsigned)(tid + 128 * i) * 16, src + tid + 128 * i);
        if (tid < DD / 4)
            cp16(smem_u32(&ts[0][0]) + (unsigned)tid * 16,
                 ((const float4*)&g_t[0][0]) + tid);
        cp_commit();
    }

#pragma unroll 1
    for (int k = 0; k < KC; k++) {
        const int cur = k & 1;
        if (k < KC - 1) {
            const int nxt = (k + 1) & 1;
            const float4* src = (const float4*)&g_W[k + 1][0][0];
            unsigned dst = smem_u32(&Ws[nxt][0]);
#pragma unroll
            for (int i = 0; i < 8; i++)
                cp16(dst + (unsigned)(tid + 128 * i) * 16, src + tid + 128 * i);
            if (tid < DD / 4)
                cp16(smem_u32(&ts[nxt][0]) + (unsigned)tid * 16,
                     ((const float4*)&g_t[k + 1][0]) + tid);
            cp_commit();
            cp_wait<1>();
        } else {
            cp_wait<0>();
        }
        __syncthreads();

        const float* Wc = Ws[cur];
        const float* tc = ts[cur];

        float mahaA = 0.0f, mahaB = 0.0f;
        // rows grouped by 4; group g needs cols [0, 4g+4) — triangular W
#pragma unroll
        for (int g = 0; g < DD / 4; g++) {
#pragma unroll
            for (int r = 0; r < 4; r++) {
                const int i = 4 * g + r;
                unsigned long long a0 = 0ull, a1 = 0ull;
                unsigned long long b0 = 0ull, b1 = 0ull;
                const ulonglong2* wr = (const ulonglong2*)(Wc + i * DD);
#pragma unroll
                for (int j = 0; j <= g; j++) {
                    ulonglong2 w2 = wr[j];
                    a0 = fma2(w2.x, pxA[2 * j], a0);
                    a1 = fma2(w2.y, pxA[2 * j + 1], a1);
                    b0 = fma2(w2.x, pxB[2 * j], b0);
                    b1 = fma2(w2.y, pxB[2 * j + 1], b1);
                }
                const float ti = tc[i];
                float2 a = unpk2(add2(a0, a1));
                float da = (a.x + a.y) - ti;
                mahaA = fmaf(da, da, mahaA);
                float2 b = unpk2(add2(b0, b1));
                float db = (b.x + b.y) - ti;
                mahaB = fmaf(db, db, mahaB);
            }
        }
        if (p0 < n) {
            float2 lw = make_float2(cs[k] - 0.5f * mahaA,
                                    cs[k] - 0.5f * mahaB);
            if (p0 + 1 < n) {
                *(float2*)&g_logits[k][p0] = lw;
            } else {
                g_logits[k][p0] = lw.x;
            }
        }
        __syncthreads();
    }
}

// ---------------- softmax pass ----------------
__global__ __launch_bounds__(256)
void gmm_softmax_kernel(float* __restrict__ out, int n) {
    const int p = blockIdx.x * 256 + threadIdx.x;
    if (p >= n) return;
    float w[KC];
    float m = -INFINITY;
#pragma unroll
    for (int k = 0; k < KC; k++) {
        w[k] = g_logits[k][p];
        m = fmaxf(m, w[k]);
    }
    float s = 0.0f;
#pragma unroll
    for (int k = 0; k < KC; k++) {
        w[k] = __expf(w[k] - m);
        s += w[k];
    }
    const float inv = 1.0f / s;
    float4* orow = (float4*)(out + (size_t)p * KC);
#pragma unroll
    for (int q = 0; q < KC / 4; q++)
        orow[q] = make_float4(w[4 * q] * inv, w[4 * q + 1] * inv,
                              w[4 * q + 2] * inv, w[4 * q + 3] * inv);
}

extern "C" void kernel_launch(void* const* d_in, const int* in_sizes, int n_in,
                              void* d_out, int out_size) {
    const float* X    = (const float*)d_in[0];  // [N, 64]
    const float* pi   = (const float*)d_in[1];  // [16]
    const float* mus  = (const float*)d_in[2];  // [16, 64]
    const float* covs = (const float*)d_in[3];  // [16, 64, 64]
    float* out = (float*)d_out;                 // [N, 16]

    const int n = in_sizes[0] / DD;

    gmm_precompute_kernel<<<KC, DD>>>(pi, mus, covs);
    const int pts_per_block = 256;  // 128 threads x 2 points
    gmm_main_kernel<<<(n + pts_per_block - 1) / pts_per_block, 128>>>(X, n);
    gmm_softmax_kernel<<<(n + 255) / 256, 256>>>(out, n);
}

// round 5
// speedup vs baseline: 1.2676x; 1.2676x over previous
#include <cuda_runtime.h>
#include <math.h>

#define KC 16
#define DD 64
#define NMAX 204800

// Precomputed per-component data: W = L^{-1} (lower-tri), t = W*mu,
// c = log(pi) - 0.5*D*log(2pi) - sum(log(diag(L)))
__device__ float g_W[KC][DD][DD];
__device__ float g_t[KC][DD];
__device__ float g_c[KC];
__device__ float g_logits[KC][NMAX];   // [K][N] scratch, coalesced writes

// ---------------- packed f32x2 helpers ----------------
__device__ __forceinline__ unsigned long long fma2(unsigned long long a,
                                                   unsigned long long b,
                                                   unsigned long long c) {
    unsigned long long d;
    asm("fma.rn.f32x2 %0, %1, %2, %3;" : "=l"(d) : "l"(a), "l"(b), "l"(c));
    return d;
}
__device__ __forceinline__ unsigned long long add2(unsigned long long a,
                                                   unsigned long long b) {
    unsigned long long d;
    asm("add.rn.f32x2 %0, %1, %2;" : "=l"(d) : "l"(a), "l"(b));
    return d;
}
__device__ __forceinline__ unsigned long long pk2(float lo, float hi) {
    unsigned long long r;
    asm("mov.b64 %0, {%1, %2};" : "=l"(r) : "f"(lo), "f"(hi));
    return r;
}
__device__ __forceinline__ float2 unpk2(unsigned long long v) {
    unsigned int lo, hi;
    asm("mov.b64 {%0, %1}, %2;" : "=r"(lo), "=r"(hi) : "l"(v));
    float2 f;
    f.x = __uint_as_float(lo);
    f.y = __uint_as_float(hi);
    return f;
}

// ---------------- cp.async helpers ----------------
__device__ __forceinline__ unsigned smem_u32(const void* p) {
    return (unsigned)__cvta_generic_to_shared(p);
}
__device__ __forceinline__ void cp16(unsigned dst, const void* src) {
    asm volatile("cp.async.cg.shared.global [%0], [%1], 16;\n"
                 :: "r"(dst), "l"(src));
}
__device__ __forceinline__ void cp_commit() {
    asm volatile("cp.async.commit_group;\n");
}
template <int N> __device__ __forceinline__ void cp_wait() {
    asm volatile("cp.async.wait_group %0;\n" :: "n"(N));
}

// ---------------- precompute v3: SMEM-resident LDL^T ----------------
// 16 blocks (one per component) x 64 threads; thread c owns COLUMN c.
// No register arrays -> no local-memory risk. Small dynamic loops in SMEM.
__global__ void __launch_bounds__(64)
gmm_precompute_kernel(const float* __restrict__ pi,
                      const float* __restrict__ mus,
                      const float* __restrict__ covs) {
    __shared__ float Ms[DD][DD + 1];   // A -> LDL columns -> L
    __shared__ float Wsm[DD][DD + 1];  // W = L^{-1}
    __shared__ float dpiv[DD];         // pivots d_j
    __shared__ float sinvd[DD];        // 1/sqrt(d_j) = 1/L[j][j]
    __shared__ float mu_s[DD];
    __shared__ float lg[DD];

    const int k = blockIdx.x;
    const int c = threadIdx.x;  // 0..63

    // load column c of cov (coalesced across threads per row i)
    for (int i = 0; i < DD; i++)
        Ms[i][c] = covs[((size_t)k * DD + i) * DD + c];
    mu_s[c] = mus[k * DD + c];
    __syncthreads();

    // ---- LDL^T (right-looking, submatrix update). After step j, column j
    // holds v_i = d_j * lunit_ij (i >= j) with Ms[j][j] = d_j.
    for (int j = 0; j < DD; j++) {
        const float dj = Ms[j][j];
        if (c == j) {
            dpiv[j] = dj;
            sinvd[j] = rsqrtf(dj);
        }
        if (c > j) {
            const float s = Ms[c][j] / dj;
            for (int i = c; i < DD; i++)
                Ms[i][c] -= Ms[i][j] * s;
        }
        __syncthreads();
    }

    // normalize columns to Cholesky L: L[i][j] = v_ij / sqrt(d_j)
    {
        const float sc = sinvd[c];
        for (int i = c; i < DD; i++) Ms[i][c] *= sc;
        lg[c] = logf(dpiv[c]);          // for logdet (parallel)
        // init W column
        for (int i = 0; i < DD; i++) Wsm[i][c] = 0.0f;
        Wsm[c][c] = 1.0f;
    }
    __syncthreads();

    // ---- triangular inverse: thread c computes column c of W = L^{-1}
    for (int j = c; j < DD; j++) {
        const float wj = Wsm[j][c] * sinvd[j];   // 1/L[j][j]
        Wsm[j][c] = wj;
        for (int i = j + 1; i < DD; i++)
            Wsm[i][c] -= Ms[i][j] * wj;
    }
    __syncthreads();

    // write W rows (coalesced across c per row i)
    for (int i = 0; i < DD; i++) g_W[k][i][c] = Wsm[i][c];

    // t[c] = row c of W dot mu
    {
        float s = 0.0f;
        for (int j = 0; j <= c; j++)
            s = fmaf(Wsm[c][j], mu_s[j], s);
        g_t[k][c] = s;
    }
    if (c == 0) {
        float sl = 0.0f;
        for (int i = 0; i < DD; i++) sl += lg[i];
        // half_logdet = 0.5 * sum(log d_i);  0.5*64*log(2pi) = 32*1.837877...
        g_c[k] = logf(pi[k]) - 32.0f * 1.8378770664093453f - 0.5f * sl;
    }
}

// ---------------- main kernel ----------------
// 128 threads/block, TWO points per thread, triangular matvec, 3 CTAs/SM.
__global__ __launch_bounds__(128, 3)
void gmm_main_kernel(const float* __restrict__ X, int n) {
    __shared__ __align__(16) float Ws[2][DD * DD];  // 2 x 16 KB
    __shared__ __align__(16) float ts[2][DD];
    __shared__ float cs[KC];

    const int tid = threadIdx.x;
    const int p0 = (blockIdx.x * 128 + tid) * 2;
    const int ld0 = (p0 < n) ? p0 : (n - 1);
    const int ld1 = (p0 + 1 < n) ? (p0 + 1) : (n - 1);

    if (tid < KC) cs[tid] = g_c[tid];

    // Load both points into packed f32x2 registers (j-packing)
    unsigned long long pxA[DD / 2], pxB[DD / 2];
    {
        const float4* xr0 = (const float4*)(X + (size_t)ld0 * DD);
        const float4* xr1 = (const float4*)(X + (size_t)ld1 * DD);
#pragma unroll
        for (int i = 0; i < DD / 4; i++) {
            float4 v = xr0[i];
            pxA[2 * i]     = pk2(v.x, v.y);
            pxA[2 * i + 1] = pk2(v.z, v.w);
            float4 u = xr1[i];
            pxB[2 * i]     = pk2(u.x, u.y);
            pxB[2 * i + 1] = pk2(u.z, u.w);
        }
    }

    // prefetch component 0 into buffer 0
    {
        const float4* src = (const float4*)&g_W[0][0][0];
        unsigned dst = smem_u32(&Ws[0][0]);
#pragma unroll
        for (int i = 0; i < 8; i++)
            cp16(dst + (unsigned)(tid + 128 * i) * 16, src + tid + 128 * i);
        if (tid < DD / 4)
            cp16(smem_u32(&ts[0][0]) + (unsigned)tid * 16,
                 ((const float4*)&g_t[0][0]) + tid);
        cp_commit();
    }

#pragma unroll 1
    for (int k = 0; k < KC; k++) {
        const int cur = k & 1;
        if (k < KC - 1) {
            const int nxt = (k + 1) & 1;
            const float4* src = (const float4*)&g_W[k + 1][0][0];
            unsigned dst = smem_u32(&Ws[nxt][0]);
#pragma unroll
            for (int i = 0; i < 8; i++)
                cp16(dst + (unsigned)(tid + 128 * i) * 16, src + tid + 128 * i);
            if (tid < DD / 4)
                cp16(smem_u32(&ts[nxt][0]) + (unsigned)tid * 16,
                     ((const float4*)&g_t[k + 1][0]) + tid);
            cp_commit();
            cp_wait<1>();
        } else {
            cp_wait<0>();
        }
        __syncthreads();

        const float* Wc = Ws[cur];
        const float* tc = ts[cur];

        float mahaA = 0.0f, mahaB = 0.0f;
        // rows grouped by 4; group g needs cols [0, 4g+4) — triangular W
#pragma unroll
        for (int g = 0; g < DD / 4; g++) {
#pragma unroll
            for (int r = 0; r < 4; r++) {
                const int i = 4 * g + r;
                unsigned long long a0 = 0ull, a1 = 0ull;
                unsigned long long b0 = 0ull, b1 = 0ull;
                const ulonglong2* wr = (const ulonglong2*)(Wc + i * DD);
#pragma unroll
                for (int j = 0; j <= g; j++) {
                    ulonglong2 w2 = wr[j];
                    a0 = fma2(w2.x, pxA[2 * j], a0);
                    a1 = fma2(w2.y, pxA[2 * j + 1], a1);
                    b0 = fma2(w2.x, pxB[2 * j], b0);
                    b1 = fma2(w2.y, pxB[2 * j + 1], b1);
                }
                const float ti = tc[i];
                float2 a = unpk2(add2(a0, a1));
                float da = (a.x + a.y) - ti;
                mahaA = fmaf(da, da, mahaA);
                float2 b = unpk2(add2(b0, b1));
                float db = (b.x + b.y) - ti;
                mahaB = fmaf(db, db, mahaB);
            }
        }
        if (p0 < n) {
            float2 lw = make_float2(cs[k] - 0.5f * mahaA,
                                    cs[k] - 0.5f * mahaB);
            if (p0 + 1 < n) {
                *(float2*)&g_logits[k][p0] = lw;
            } else {
                g_logits[k][p0] = lw.x;
            }
        }
        __syncthreads();
    }
}

// ---------------- softmax pass ----------------
__global__ __launch_bounds__(256)
void gmm_softmax_kernel(float* __restrict__ out, int n) {
    const int p = blockIdx.x * 256 + threadIdx.x;
    if (p >= n) return;
    float w[KC];
    float m = -INFINITY;
#pragma unroll
    for (int k = 0; k < KC; k++) {
        w[k] = g_logits[k][p];
        m = fmaxf(m, w[k]);
    }
    float s = 0.0f;
#pragma unroll
    for (int k = 0; k < KC; k++) {
        w[k] = __expf(w[k] - m);
        s += w[k];
    }
    const float inv = 1.0f / s;
    float4* orow = (float4*)(out + (size_t)p * KC);
#pragma unroll
    for (int q = 0; q < KC / 4; q++)
        orow[q] = make_float4(w[4 * q] * inv, w[4 * q + 1] * inv,
                              w[4 * q + 2] * inv, w[4 * q + 3] * inv);
}

extern "C" void kernel_launch(void* const* d_in, const int* in_sizes, int n_in,
                              void* d_out, int out_size) {
    const float* X    = (const float*)d_in[0];  // [N, 64]
    const float* pi   = (const float*)d_in[1];  // [16]
    const float* mus  = (const float*)d_in[2];  // [16, 64]
    const float* covs = (const float*)d_in[3];  // [16, 64, 64]
    float* out = (float*)d_out;                 // [N, 16]

    const int n = in_sizes[0] / DD;

    gmm_precompute_kernel<<<KC, DD>>>(pi, mus, covs);
    const int pts_per_block = 256;  // 128 threads x 2 points
    gmm_main_kernel<<<(n + pts_per_block - 1) / pts_per_block, 128>>>(X, n);
    gmm_softmax_kernel<<<(n + 255) / 256, 256>>>(out, n);
}

// round 6
// speedup vs baseline: 1.5645x; 1.2343x over previous
#include <cuda_runtime.h>
#include <math.h>

#define KC 16
#define DD 64
#define NMAX 204800

// Precomputed per-component data: W = L^{-1} (lower-tri), t = W*mu,
// c = log(pi) - 0.5*D*log(2pi) - sum(log(diag(L)))
__device__ float g_W[KC][DD][DD];
__device__ float g_t[KC][DD];
__device__ float g_c[KC];
__device__ float g_logits[KC][NMAX];   // [K][N] scratch, coalesced writes

// ---------------- packed f32x2 helpers ----------------
__device__ __forceinline__ unsigned long long fma2(unsigned long long a,
                                                   unsigned long long b,
                                                   unsigned long long c) {
    unsigned long long d;
    asm("fma.rn.f32x2 %0, %1, %2, %3;" : "=l"(d) : "l"(a), "l"(b), "l"(c));
    return d;
}
__device__ __forceinline__ unsigned long long add2(unsigned long long a,
                                                   unsigned long long b) {
    unsigned long long d;
    asm("add.rn.f32x2 %0, %1, %2;" : "=l"(d) : "l"(a), "l"(b));
    return d;
}
__device__ __forceinline__ unsigned long long pk2(float lo, float hi) {
    unsigned long long r;
    asm("mov.b64 %0, {%1, %2};" : "=l"(r) : "f"(lo), "f"(hi));
    return r;
}
__device__ __forceinline__ float2 unpk2(unsigned long long v) {
    unsigned int lo, hi;
    asm("mov.b64 {%0, %1}, %2;" : "=r"(lo), "=r"(hi) : "l"(v));
    float2 f;
    f.x = __uint_as_float(lo);
    f.y = __uint_as_float(hi);
    return f;
}

// ---------------- cp.async helpers ----------------
__device__ __forceinline__ unsigned smem_u32(const void* p) {
    return (unsigned)__cvta_generic_to_shared(p);
}
__device__ __forceinline__ void cp16(unsigned dst, const void* src) {
    asm volatile("cp.async.cg.shared.global [%0], [%1], 16;\n"
                 :: "r"(dst), "l"(src));
}
__device__ __forceinline__ void cp_commit() {
    asm volatile("cp.async.commit_group;\n");
}
template <int N> __device__ __forceinline__ void cp_wait() {
    asm volatile("cp.async.wait_group %0;\n" :: "n"(N));
}

// ---------------- precompute v4: row-in-registers, static loops ----------
// 16 blocks x 64 threads. Thread r owns ROW r of the matrix in registers.
// All loops have compile-time bounds; dynamic behavior only via predication.
// SMEM is only used for read-only broadcast (no alias hazards).
__global__ void __launch_bounds__(64)
gmm_precompute_kernel(const float* __restrict__ pi,
                      const float* __restrict__ mus,
                      const float* __restrict__ covs) {
    __shared__ float colbuf[2][DD];    // published column (double-buffered)
    __shared__ float rinv[DD];         // 1/L[j][j]
    __shared__ float Ls[DD][DD + 1];   // L (lower), read-only in phase 2
    __shared__ float Wsm[DD][DD + 1];  // W rows for t computation
    __shared__ float mu_s[DD];
    __shared__ float lg[DD];

    const int k = blockIdx.x;
    const int r = threadIdx.x;  // 0..63

    // load row r of cov into registers (vectorized)
    float a[DD];
    {
        const float4* src = (const float4*)(covs + ((size_t)k * DD + r) * DD);
#pragma unroll
        for (int i = 0; i < DD / 4; i++) {
            float4 v = src[i];
            a[4 * i] = v.x; a[4 * i + 1] = v.y;
            a[4 * i + 2] = v.z; a[4 * i + 3] = v.w;
        }
    }
    mu_s[r] = mus[k * DD + r];

    // ---- right-looking Cholesky, rows in registers ----
    float lrow[DD];
    float d_own = 1.0f;
#pragma unroll
    for (int j = 0; j < DD; j++) {
        colbuf[j & 1][r] = a[j];       // publish column j (one scalar, static idx)
        __syncthreads();
        const float dj = colbuf[j & 1][j];
        const float rs = rsqrtf(dj);
        const float invd = rs * rs;
        lrow[j] = a[j] * rs;           // L[r][j] (valid for r >= j)
        if (r == j) d_own = dj;
        const float s = a[j] * invd;
        if (r > j) {
#pragma unroll
            for (int q = j + 1; q < DD; q++)
                a[q] = fmaf(-s, colbuf[j & 1][q], a[q]);
        }
        // no trailing sync needed: next step writes the other buffer, and
        // the barrier inside step j+1 orders step-j reads vs step-j+2 writes.
    }

    rinv[r] = rsqrtf(d_own);
    lg[r] = logf(d_own);
#pragma unroll
    for (int j = 0; j < DD; j++)
        Ls[r][j] = (r >= j) ? lrow[j] : 0.0f;
    __syncthreads();

    // ---- triangular inverse: thread c (=r) computes W column c ----
    // w[j] = 0 for j < c automatically keeps the static dot correct.
    float w[DD];
#pragma unroll
    for (int i = 0; i < DD; i++)
        w[i] = (i == r) ? rinv[r] : 0.0f;
#pragma unroll
    for (int i = 1; i < DD; i++) {
        float acc = 0.0f;
#pragma unroll
        for (int j = 0; j < i; j++)
            acc = fmaf(Ls[i][j], w[j], acc);   // broadcast LDS
        if (i > r) w[i] = -acc * rinv[i];
    }

    // write W (coalesced: thread r owns column r) + stage rows in SMEM
#pragma unroll
    for (int i = 0; i < DD; i++) {
        g_W[k][i][r] = w[i];
        Wsm[i][r] = w[i];
    }
    __syncthreads();

    // t[r] = row r of W dot mu
    {
        float s = 0.0f;
#pragma unroll
        for (int j = 0; j < DD; j++)
            s = fmaf(Wsm[r][j], mu_s[j], s);
        g_t[k][r] = s;
    }
    if (r == 0) {
        float sl = 0.0f;
#pragma unroll
        for (int i = 0; i < DD; i++) sl += lg[i];
        // half_logdet = 0.5 * sum(log d_i)
        g_c[k] = logf(pi[k]) - 32.0f * 1.8378770664093453f - 0.5f * sl;
    }
}

// ---------------- main kernel (proven R3 config) ----------------
// 128 threads/block, TWO points per thread, triangular matvec, 3 CTAs/SM.
__global__ __launch_bounds__(128, 3)
void gmm_main_kernel(const float* __restrict__ X, int n) {
    __shared__ __align__(16) float Ws[2][DD * DD];  // 2 x 16 KB
    __shared__ __align__(16) float ts[2][DD];
    __shared__ float cs[KC];

    const int tid = threadIdx.x;
    const int p0 = (blockIdx.x * 128 + tid) * 2;
    const int ld0 = (p0 < n) ? p0 : (n - 1);
    const int ld1 = (p0 + 1 < n) ? (p0 + 1) : (n - 1);

    if (tid < KC) cs[tid] = g_c[tid];

    // Load both points into packed f32x2 registers (j-packing)
    unsigned long long pxA[DD / 2], pxB[DD / 2];
    {
        const float4* xr0 = (const float4*)(X + (size_t)ld0 * DD);
        const float4* xr1 = (const float4*)(X + (size_t)ld1 * DD);
#pragma unroll
        for (int i = 0; i < DD / 4; i++) {
            float4 v = xr0[i];
            pxA[2 * i]     = pk2(v.x, v.y);
            pxA[2 * i + 1] = pk2(v.z, v.w);
            float4 u = xr1[i];
            pxB[2 * i]     = pk2(u.x, u.y);
            pxB[2 * i + 1] = pk2(u.z, u.w);
        }
    }

    // prefetch component 0 into buffer 0
    {
        const float4* src = (const float4*)&g_W[0][0][0];
        unsigned dst = smem_u32(&Ws[0][0]);
#pragma unroll
        for (int i = 0; i < 8; i++)
            cp16(dst + (unsigned)(tid + 128 * i) * 16, src + tid + 128 * i);
        if (tid < DD / 4)
            cp16(smem_u32(&ts[0][0]) + (unsigned)tid * 16,
                 ((const float4*)&g_t[0][0]) + tid);
        cp_commit();
    }

#pragma unroll 1
    for (int k = 0; k < KC; k++) {
        const int cur = k & 1;
        if (k < KC - 1) {
            const int nxt = (k + 1) & 1;
            const float4* src = (const float4*)&g_W[k + 1][0][0];
            unsigned dst = smem_u32(&Ws[nxt][0]);
#pragma unroll
            for (int i = 0; i < 8; i++)
                cp16(dst + (unsigned)(tid + 128 * i) * 16, src + tid + 128 * i);
            if (tid < DD / 4)
                cp16(smem_u32(&ts[nxt][0]) + (unsigned)tid * 16,
                     ((const float4*)&g_t[k + 1][0]) + tid);
            cp_commit();
            cp_wait<1>();
        } else {
            cp_wait<0>();
        }
        __syncthreads();

        const float* Wc = Ws[cur];
        const float* tc = ts[cur];

        float mahaA = 0.0f, mahaB = 0.0f;
        // rows grouped by 4; group g needs cols [0, 4g+4) — triangular W
#pragma unroll
        for (int g = 0; g < DD / 4; g++) {
#pragma unroll
            for (int r = 0; r < 4; r++) {
                const int i = 4 * g + r;
                unsigned long long a0 = 0ull, a1 = 0ull;
                unsigned long long b0 = 0ull, b1 = 0ull;
                const ulonglong2* wr = (const ulonglong2*)(Wc + i * DD);
#pragma unroll
                for (int j = 0; j <= g; j++) {
                    ulonglong2 w2 = wr[j];
                    a0 = fma2(w2.x, pxA[2 * j], a0);
                    a1 = fma2(w2.y, pxA[2 * j + 1], a1);
                    b0 = fma2(w2.x, pxB[2 * j], b0);
                    b1 = fma2(w2.y, pxB[2 * j + 1], b1);
                }
                const float ti = tc[i];
                float2 a = unpk2(add2(a0, a1));
                float da = (a.x + a.y) - ti;
                mahaA = fmaf(da, da, mahaA);
                float2 b = unpk2(add2(b0, b1));
                float db = (b.x + b.y) - ti;
                mahaB = fmaf(db, db, mahaB);
            }
        }
        if (p0 < n) {
            float2 lw = make_float2(cs[k] - 0.5f * mahaA,
                                    cs[k] - 0.5f * mahaB);
            if (p0 + 1 < n) {
                *(float2*)&g_logits[k][p0] = lw;
            } else {
                g_logits[k][p0] = lw.x;
            }
        }
        __syncthreads();
    }
}

// ---------------- softmax pass ----------------
__global__ __launch_bounds__(256)
void gmm_softmax_kernel(float* __restrict__ out, int n) {
    const int p = blockIdx.x * 256 + threadIdx.x;
    if (p >= n) return;
    float w[KC];
    float m = -INFINITY;
#pragma unroll
    for (int k = 0; k < KC; k++) {
        w[k] = g_logits[k][p];
        m = fmaxf(m, w[k]);
    }
    float s = 0.0f;
#pragma unroll
    for (int k = 0; k < KC; k++) {
        w[k] = __expf(w[k] - m);
        s += w[k];
    }
    const float inv = 1.0f / s;
    float4* orow = (float4*)(out + (size_t)p * KC);
#pragma unroll
    for (int q = 0; q < KC / 4; q++)
        orow[q] = make_float4(w[4 * q] * inv, w[4 * q + 1] * inv,
                              w[4 * q + 2] * inv, w[4 * q + 3] * inv);
}

extern "C" void kernel_launch(void* const* d_in, const int* in_sizes, int n_in,
                              void* d_out, int out_size) {
    const float* X    = (const float*)d_in[0];  // [N, 64]
    const float* pi   = (const float*)d_in[1];  // [16]
    const float* mus  = (const float*)d_in[2];  // [16, 64]
    const float* covs = (const float*)d_in[3];  // [16, 64, 64]
    float* out = (float*)d_out;                 // [N, 16]

    const int n = in_sizes[0] / DD;

    gmm_precompute_kernel<<<KC, DD>>>(pi, mus, covs);
    const int pts_per_block = 256;  // 128 threads x 2 points
    gmm_main_kernel<<<(n + pts_per_block - 1) / pts_per_block, 128>>>(X, n);
    gmm_softmax_kernel<<<(n + 255) / 256, 256>>>(out, n);
}